// round 3
// baseline (speedup 1.0000x reference)
#include <cuda_runtime.h>
#include <cuda_fp16.h>
#include <cstdint>
#include <cstddef>

// ---------------- Problem constants ----------------
#define B_   32
#define S_   2048
#define HLEN 1024
#define VLEN 1024
#define HID  1024

// ---------------- Scratch (static device globals; no allocs allowed) ------
__device__ __align__(16) __half g_Vh[(size_t)B_ * S_ * VLEN];   // 128 MB
__device__ __align__(16) __half g_Uh[(size_t)HID * VLEN];       // 2 MB
__device__ __align__(16) float  g_hp[B_ * HID];                 // h_proj + bias
__device__ __align__(16) float  g_e[B_ * S_];                   // e scores -> beta
__device__ __align__(16) float  g_part[4 * B_ * VLEN];          // out partials

// ---------------- Helpers ----------------
__device__ __forceinline__ uint32_t smem_u32(const void* p) {
    return (uint32_t)__cvta_generic_to_shared(p);
}

__device__ __forceinline__ void ldsm_x4(uint32_t* r, uint32_t addr) {
    asm volatile("ldmatrix.sync.aligned.m8n8.x4.shared.b16 {%0,%1,%2,%3},[%4];"
                 : "=r"(r[0]), "=r"(r[1]), "=r"(r[2]), "=r"(r[3]) : "r"(addr));
}

__device__ __forceinline__ void mma16816(float* c, const uint32_t* a, const uint32_t* b) {
    asm volatile(
        "mma.sync.aligned.m16n8k16.row.col.f32.f16.f16.f32 "
        "{%0,%1,%2,%3},{%4,%5,%6,%7},{%8,%9},{%0,%1,%2,%3};"
        : "+f"(c[0]), "+f"(c[1]), "+f"(c[2]), "+f"(c[3])
        : "r"(a[0]), "r"(a[1]), "r"(a[2]), "r"(a[3]), "r"(b[0]), "r"(b[1]));
}

// ---------------- Kernel 1: fp32 -> fp16 convert ----------------
__global__ void cvt_kernel(const float* __restrict__ src, __half* __restrict__ dst, size_t n4) {
    size_t i = (size_t)blockIdx.x * blockDim.x + threadIdx.x;
    if (i >= n4) return;
    float4 v = reinterpret_cast<const float4*>(src)[i];
    __half2* d2 = reinterpret_cast<__half2*>(dst) + i * 2;
    d2[0] = __floats2half2_rn(v.x, v.y);
    d2[1] = __floats2half2_rn(v.z, v.w);
}

// ---------------- Kernel 2: h_proj[b,d] = h[b]·W_w[d] + W_b[d] ------------
__global__ void hproj_kernel(const float* __restrict__ h,
                             const float* __restrict__ Ww,
                             const float* __restrict__ Wb) {
    int w = (blockIdx.x * blockDim.x + threadIdx.x) >> 5;   // global warp id
    int lane = threadIdx.x & 31;
    int b = w >> 10;           // HID = 1024 warps per batch
    int d = w & 1023;
    if (b >= B_) return;
    const float* hv = h + (size_t)b * HLEN;
    const float* wr = Ww + (size_t)d * HLEN;
    float acc = 0.f;
    #pragma unroll 8
    for (int v = lane; v < HLEN; v += 32) acc += hv[v] * wr[v];
    #pragma unroll
    for (int o = 16; o; o >>= 1) acc += __shfl_xor_sync(0xffffffffu, acc, o);
    if (lane == 0) g_hp[b * HID + d] = acc + Wb[d];
}

// ---------------- Kernel 3: fused e = w·tanh(hp + V U^T) ----------------
// Block: 256 threads (8 warps, 4(M) x 2(N)); tile M=128 (s), N=128 (d), K=32.
// grid = (S/128, B)
#define KT 32
#define LDT 40   // half stride (80B) -> conflict-free ldmatrix
__global__ void e_kernel(const float* __restrict__ ww) {
    const int lane = threadIdx.x & 31;
    const int warp = threadIdx.x >> 5;
    const int wm = warp & 3;      // 0..3 -> 32 rows each
    const int wn = warp >> 2;     // 0..1 -> 64 cols each
    const int b  = blockIdx.y;
    const int s0 = blockIdx.x * 128;

    __shared__ __half Va[128 * LDT];
    __shared__ __half Ua[128 * LDT];
    __shared__ float  e_red[128];

    if (threadIdx.x < 128) e_red[threadIdx.x] = 0.f;

    const __half* Vb  = g_Vh + ((size_t)b * S_ + s0) * VLEN;
    const float*  hpb = g_hp + b * HID;

    float e_part[4] = {0.f, 0.f, 0.f, 0.f};

    // tile-load index precompute
    const int lrow  = threadIdx.x >> 1;
    const int lpart = threadIdx.x & 1;

    for (int n0 = 0; n0 < HID; n0 += 128) {
        float acc[2][8][4] = {};
        for (int k0 = 0; k0 < VLEN; k0 += KT) {
            __syncthreads();
            {
                const uint4* sv = reinterpret_cast<const uint4*>(Vb + (size_t)lrow * VLEN + k0 + lpart * 16);
                uint4* dv = reinterpret_cast<uint4*>(Va + lrow * LDT + lpart * 16);
                dv[0] = sv[0];
                dv[1] = sv[1];
                const uint4* su = reinterpret_cast<const uint4*>(g_Uh + (size_t)(n0 + lrow) * VLEN + k0 + lpart * 16);
                uint4* du = reinterpret_cast<uint4*>(Ua + lrow * LDT + lpart * 16);
                du[0] = su[0];
                du[1] = su[1];
            }
            __syncthreads();

            #pragma unroll
            for (int ks = 0; ks < 2; ks++) {
                const int kb = ks * 16;
                uint32_t a[2][4];
                #pragma unroll
                for (int mf = 0; mf < 2; mf++) {
                    int row = wm * 32 + mf * 16 + (lane & 15);
                    int col = kb + (lane >> 4) * 8;
                    ldsm_x4(a[mf], smem_u32(&Va[row * LDT + col]));
                }
                uint32_t bb[4][4];
                #pragma unroll
                for (int nf2 = 0; nf2 < 4; nf2++) {
                    int nrow = wn * 64 + nf2 * 16 + (lane >> 4) * 8 + (lane & 7);
                    int col  = kb + ((lane >> 3) & 1) * 8;
                    ldsm_x4(bb[nf2], smem_u32(&Ua[nrow * LDT + col]));
                }
                #pragma unroll
                for (int mf = 0; mf < 2; mf++)
                    #pragma unroll
                    for (int nf = 0; nf < 8; nf++)
                        mma16816(acc[mf][nf], a[mf], &bb[nf >> 1][(nf & 1) * 2]);
            }
        }
        // Fold tanh + w_w dot on accumulator fragments
        #pragma unroll
        for (int mf = 0; mf < 2; mf++) {
            #pragma unroll
            for (int nf = 0; nf < 8; nf++) {
                int col = n0 + wn * 64 + nf * 8 + (lane & 3) * 2;
                float h0 = hpb[col], h1 = hpb[col + 1];
                float w0 = ww[col],  w1 = ww[col + 1];
                e_part[mf * 2 + 0] += tanhf(acc[mf][nf][0] + h0) * w0
                                    + tanhf(acc[mf][nf][1] + h1) * w1;
                e_part[mf * 2 + 1] += tanhf(acc[mf][nf][2] + h0) * w0
                                    + tanhf(acc[mf][nf][3] + h1) * w1;
            }
        }
    }

    // reduce over the 4 lanes sharing each row
    #pragma unroll
    for (int i = 0; i < 4; i++) {
        e_part[i] += __shfl_xor_sync(0xffffffffu, e_part[i], 1);
        e_part[i] += __shfl_xor_sync(0xffffffffu, e_part[i], 2);
    }
    if ((lane & 3) == 0) {
        #pragma unroll
        for (int i = 0; i < 4; i++) {
            int r = wm * 32 + (i >> 1) * 16 + (i & 1) * 8 + (lane >> 2);
            atomicAdd(&e_red[r], e_part[i]);
        }
    }
    __syncthreads();
    if (threadIdx.x < 128)
        g_e[b * S_ + s0 + threadIdx.x] = e_red[threadIdx.x];
}

// ---------------- Kernel 4: softmax over S (in-place on g_e) -------------
__global__ void softmax_kernel() {
    int b = blockIdx.x;
    float* row = g_e + (size_t)b * S_;
    __shared__ float red[256];
    float m = -1e30f;
    for (int s = threadIdx.x; s < S_; s += 256) m = fmaxf(m, row[s]);
    red[threadIdx.x] = m; __syncthreads();
    for (int o = 128; o > 0; o >>= 1) {
        if (threadIdx.x < o) red[threadIdx.x] = fmaxf(red[threadIdx.x], red[threadIdx.x + o]);
        __syncthreads();
    }
    m = red[0]; __syncthreads();
    float sum = 0.f;
    for (int s = threadIdx.x; s < S_; s += 256) {
        float v = __expf(row[s] - m);
        row[s] = v;
        sum += v;
    }
    red[threadIdx.x] = sum; __syncthreads();
    for (int o = 128; o > 0; o >>= 1) {
        if (threadIdx.x < o) red[threadIdx.x] += red[threadIdx.x + o];
        __syncthreads();
    }
    float inv = 1.f / red[0];
    for (int s = threadIdx.x; s < S_; s += 256) row[s] *= inv;
}

// ---------------- Kernel 5: out partials over s-splits -------------------
// grid (4 vchunks, B, 4 schunks), 256 threads
__global__ void out_part_kernel(const float* __restrict__ V) {
    int vc = blockIdx.x, b = blockIdx.y, sc = blockIdx.z;
    int v = vc * 256 + threadIdx.x;
    const float* beta = g_e + (size_t)b * S_ + sc * 512;
    const float* Vp   = V + ((size_t)b * S_ + sc * 512) * VLEN + v;
    float acc = 0.f;
    #pragma unroll 8
    for (int s = 0; s < 512; s++)
        acc += beta[s] * Vp[(size_t)s * VLEN];
    g_part[((size_t)sc * B_ + b) * VLEN + v] = acc;
}

// ---------------- Kernel 6: reduce partials --------------------------------
__global__ void out_reduce_kernel(float* __restrict__ out) {
    int i = blockIdx.x * 256 + threadIdx.x;   // 32768 total
    const int stride = B_ * VLEN;
    out[i] = g_part[i] + g_part[stride + i] + g_part[2 * stride + i] + g_part[3 * stride + i];
}

// ---------------- Launch ----------------
extern "C" void kernel_launch(void* const* d_in, const int* in_sizes, int n_in,
                              void* d_out, int out_size) {
    const float* h   = (const float*)d_in[0];   // [B, HLEN]
    const float* V   = (const float*)d_in[1];   // [B, S, VLEN]
    const float* W_w = (const float*)d_in[2];   // [HID, HLEN]
    const float* W_b = (const float*)d_in[3];   // [HID]
    const float* U_w = (const float*)d_in[4];   // [HID, VLEN]
    const float* w_w = (const float*)d_in[5];   // [HID]
    float* out = (float*)d_out;                 // [B, VLEN]

    __half* Vh; cudaGetSymbolAddress((void**)&Vh, g_Vh);
    __half* Uh; cudaGetSymbolAddress((void**)&Uh, g_Uh);

    // 1. fp32 -> fp16 conversions
    {
        size_t n4 = (size_t)B_ * S_ * VLEN / 4;
        cvt_kernel<<<(unsigned)((n4 + 255) / 256), 256>>>(V, Vh, n4);
        size_t u4 = (size_t)HID * VLEN / 4;
        cvt_kernel<<<(unsigned)((u4 + 255) / 256), 256>>>(U_w, Uh, u4);
    }
    // 2. h_proj
    hproj_kernel<<<(B_ * HID) / 8, 256>>>(h, W_w, W_b);
    // 3. fused e scores
    {
        dim3 grid(S_ / 128, B_);
        e_kernel<<<grid, 256>>>(w_w);
    }
    // 4. softmax
    softmax_kernel<<<B_, 256>>>();
    // 5. weighted sum partials
    {
        dim3 grid(VLEN / 256, B_, 4);
        out_part_kernel<<<grid, 256>>>(V);
    }
    // 6. reduce
    out_reduce_kernel<<<(B_ * VLEN) / 256, 256>>>(out);
}

// round 6
// speedup vs baseline: 1.5380x; 1.5380x over previous
#include <cuda_runtime.h>
#include <cuda_fp16.h>
#include <cstdint>
#include <cstddef>

// ---------------- Problem constants ----------------
#define B_   32
#define S_   2048
#define HLEN 1024
#define VLEN 1024
#define HID  1024

// ---------------- Scratch (static device globals; no allocs allowed) ------
__device__ __align__(16) __half g_Vh[(size_t)B_ * S_ * VLEN];   // 128 MB
__device__ __align__(16) __half g_Uh[(size_t)HID * VLEN];       // 2 MB
__device__ __align__(16) float  g_hp[B_ * HID];                 // h_proj + bias
__device__ __align__(16) float  g_e[B_ * S_];                   // e scores -> beta
__device__ __align__(16) float  g_part[4 * B_ * VLEN];          // out partials

// ---------------- Helpers ----------------
__device__ __forceinline__ uint32_t smem_u32(const void* p) {
    return (uint32_t)__cvta_generic_to_shared(p);
}

__device__ __forceinline__ void ldsm_x4(uint32_t* r, uint32_t addr) {
    asm volatile("ldmatrix.sync.aligned.m8n8.x4.shared.b16 {%0,%1,%2,%3},[%4];"
                 : "=r"(r[0]), "=r"(r[1]), "=r"(r[2]), "=r"(r[3]) : "r"(addr));
}

__device__ __forceinline__ void mma16816(float* c, const uint32_t* a, const uint32_t* b) {
    asm volatile(
        "mma.sync.aligned.m16n8k16.row.col.f32.f16.f16.f32 "
        "{%0,%1,%2,%3},{%4,%5,%6,%7},{%8,%9},{%0,%1,%2,%3};"
        : "+f"(c[0]), "+f"(c[1]), "+f"(c[2]), "+f"(c[3])
        : "r"(a[0]), "r"(a[1]), "r"(a[2]), "r"(a[3]), "r"(b[0]), "r"(b[1]));
}

__device__ __forceinline__ void cp_async16(uint32_t dst, const void* src) {
    asm volatile("cp.async.cg.shared.global [%0], [%1], 16;" :: "r"(dst), "l"(src) : "memory");
}
#define CP_COMMIT() asm volatile("cp.async.commit_group;" ::: "memory")
#define CP_WAIT(n)  asm volatile("cp.async.wait_group %0;" :: "n"(n) : "memory")

// ---------------- Kernel 1: fp32 -> fp16 convert ----------------
__global__ void cvt_kernel(const float* __restrict__ src, __half* __restrict__ dst, size_t n4) {
    size_t i = (size_t)blockIdx.x * blockDim.x + threadIdx.x;
    if (i >= n4) return;
    float4 v = reinterpret_cast<const float4*>(src)[i];
    __half2* d2 = reinterpret_cast<__half2*>(dst) + i * 2;
    d2[0] = __floats2half2_rn(v.x, v.y);
    d2[1] = __floats2half2_rn(v.z, v.w);
}

// ---------------- Kernel 2: h_proj[b,d] = h[b]·W_w[d] + W_b[d] ------------
__global__ void hproj_kernel(const float* __restrict__ h,
                             const float* __restrict__ Ww,
                             const float* __restrict__ Wb) {
    int w = (blockIdx.x * blockDim.x + threadIdx.x) >> 5;
    int lane = threadIdx.x & 31;
    int b = w >> 10;
    int d = w & 1023;
    if (b >= B_) return;
    const float* hv = h + (size_t)b * HLEN;
    const float* wr = Ww + (size_t)d * HLEN;
    float acc = 0.f;
    #pragma unroll 8
    for (int v = lane; v < HLEN; v += 32) acc += hv[v] * wr[v];
    #pragma unroll
    for (int o = 16; o; o >>= 1) acc += __shfl_xor_sync(0xffffffffu, acc, o);
    if (lane == 0) g_hp[b * HID + d] = acc + Wb[d];
}

// ---------------- Kernel 3: fused e = w·tanh(hp + V U^T) ----------------
// 3-stage cp.async pipelined HMMA GEMM.
// Block: 256 threads (8 warps: 4(M) x 2(N)). Tile M=128(s), N=128(d), K=64.
// smem per stage: A[128][64] + B[128][64] halves, SW128-swizzled 128B rows.
// grid = (S/128, B). 2 CTAs/SM.
#define BK 64
#define STAGES 3
#define STAGE_BYTES (2 * 128 * BK * 2)   // 32768 (A 16K + B 16K)
#define E_SMEM (STAGES * STAGE_BYTES + 512)

__global__ void __launch_bounds__(256, 2) e_kernel(const float* __restrict__ ww) {
    extern __shared__ char smem[];
    float* e_red = reinterpret_cast<float*>(smem + STAGES * STAGE_BYTES);

    const int tid  = threadIdx.x;
    const int lane = tid & 31;
    const int warp = tid >> 5;
    const int wm = warp & 3;     // 0..3 -> 32 rows each
    const int wn = warp >> 2;    // 0..1 -> 64 cols each
    const int b  = blockIdx.y;
    const int s0 = blockIdx.x * 128;

    const __half* Abase = g_Vh + ((size_t)b * S_ + s0) * VLEN;
    const float*  hpb   = g_hp + b * HID;

    if (tid < 128) e_red[tid] = 0.f;

    // ---- tile loader: 2048 x 16B chunks per tile, 8 per thread ----
    auto issue = [&](int t) {
        const int n0 = (t >> 4) << 7;         // n-block of 128 (changes every 16 tiles)
        const int k0 = (t & 15) << 6;         // k offset (64 per tile)
        char* stg = smem + (t % STAGES) * STAGE_BYTES;
        #pragma unroll
        for (int j = 0; j < 8; ++j) {
            const int i   = tid + j * 256;    // 0..2047
            const int isB = i >> 10;
            const int r   = (i >> 3) & 127;
            const int c16 = i & 7;
            const __half* src = isB
                ? (g_Uh + (size_t)(n0 + r) * VLEN + k0 + c16 * 8)
                : (Abase + (size_t)r * VLEN + k0 + c16 * 8);
            uint32_t off = (r << 7) + (c16 << 4);
            off ^= (off >> 3) & 0x70;         // SW128 swizzle
            cp_async16(smem_u32(stg + isB * 16384 + off), src);
        }
        CP_COMMIT();
    };

    issue(0);
    issue(1);

    float acc[2][8][4] = {};
    float e_part[4] = {0.f, 0.f, 0.f, 0.f};

    for (int t = 0; t < 128; ++t) {
        CP_WAIT(1);            // tile t resident (t+1 may still be in flight)
        __syncthreads();       // all warps past here => all done reading stage (t+2)%3
        if (t + 2 < 128) issue(t + 2);

        const char* stg = smem + (t % STAGES) * STAGE_BYTES;

        #pragma unroll
        for (int ks = 0; ks < 4; ++ks) {
            uint32_t a[2][4];
            #pragma unroll
            for (int mf = 0; mf < 2; ++mf) {
                const int row = wm * 32 + mf * 16 + (lane & 15);
                uint32_t off = (row << 7) + ((ks * 16 + (lane >> 4) * 8) << 1);
                off ^= (off >> 3) & 0x70;
                ldsm_x4(a[mf], smem_u32(stg + off));
            }
            uint32_t bb[4][4];
            #pragma unroll
            for (int nf2 = 0; nf2 < 4; ++nf2) {
                const int nrow = wn * 64 + nf2 * 16 + (lane >> 4) * 8 + (lane & 7);
                uint32_t off = (nrow << 7) + ((ks * 16 + ((lane >> 3) & 1) * 8) << 1);
                off ^= (off >> 3) & 0x70;
                ldsm_x4(bb[nf2], smem_u32(stg + 16384 + off));
            }
            #pragma unroll
            for (int mf = 0; mf < 2; ++mf)
                #pragma unroll
                for (int nf = 0; nf < 8; ++nf)
                    mma16816(acc[mf][nf], a[mf], &bb[nf >> 1][(nf & 1) * 2]);
        }

        if ((t & 15) == 15) {
            // ---- fold tanh + w_w dot on this 128-col n-block, reset acc ----
            const int n0 = (t >> 4) << 7;
            #pragma unroll
            for (int mf = 0; mf < 2; ++mf) {
                #pragma unroll
                for (int nf = 0; nf < 8; ++nf) {
                    const int col = n0 + wn * 64 + nf * 8 + (lane & 3) * 2;
                    const float h0 = hpb[col], h1 = hpb[col + 1];
                    const float w0 = ww[col],  w1 = ww[col + 1];
                    e_part[mf * 2 + 0] += tanhf(acc[mf][nf][0] + h0) * w0
                                        + tanhf(acc[mf][nf][1] + h1) * w1;
                    e_part[mf * 2 + 1] += tanhf(acc[mf][nf][2] + h0) * w0
                                        + tanhf(acc[mf][nf][3] + h1) * w1;
                    acc[mf][nf][0] = 0.f; acc[mf][nf][1] = 0.f;
                    acc[mf][nf][2] = 0.f; acc[mf][nf][3] = 0.f;
                }
            }
        }
    }

    // reduce over the 4 lanes sharing each row
    #pragma unroll
    for (int i = 0; i < 4; i++) {
        e_part[i] += __shfl_xor_sync(0xffffffffu, e_part[i], 1);
        e_part[i] += __shfl_xor_sync(0xffffffffu, e_part[i], 2);
    }
    if ((lane & 3) == 0) {
        #pragma unroll
        for (int i = 0; i < 4; i++) {
            const int r = wm * 32 + (i >> 1) * 16 + (i & 1) * 8 + (lane >> 2);
            atomicAdd(&e_red[r], e_part[i]);
        }
    }
    __syncthreads();
    if (tid < 128)
        g_e[(size_t)b * S_ + s0 + tid] = e_red[tid];
}

// ---------------- Kernel 4: softmax over S (in-place on g_e) -------------
__global__ void softmax_kernel() {
    int b = blockIdx.x;
    float* row = g_e + (size_t)b * S_;
    __shared__ float red[256];
    float m = -1e30f;
    for (int s = threadIdx.x; s < S_; s += 256) m = fmaxf(m, row[s]);
    red[threadIdx.x] = m; __syncthreads();
    for (int o = 128; o > 0; o >>= 1) {
        if (threadIdx.x < o) red[threadIdx.x] = fmaxf(red[threadIdx.x], red[threadIdx.x + o]);
        __syncthreads();
    }
    m = red[0]; __syncthreads();
    float sum = 0.f;
    for (int s = threadIdx.x; s < S_; s += 256) {
        float v = __expf(row[s] - m);
        row[s] = v;
        sum += v;
    }
    red[threadIdx.x] = sum; __syncthreads();
    for (int o = 128; o > 0; o >>= 1) {
        if (threadIdx.x < o) red[threadIdx.x] += red[threadIdx.x + o];
        __syncthreads();
    }
    float inv = 1.f / red[0];
    for (int s = threadIdx.x; s < S_; s += 256) row[s] *= inv;
}

// ---------------- Kernel 5: out partials over s-splits -------------------
__global__ void out_part_kernel(const float* __restrict__ V) {
    int vc = blockIdx.x, b = blockIdx.y, sc = blockIdx.z;
    int v = vc * 256 + threadIdx.x;
    const float* beta = g_e + (size_t)b * S_ + sc * 512;
    const float* Vp   = V + ((size_t)b * S_ + sc * 512) * VLEN + v;
    float acc = 0.f;
    #pragma unroll 8
    for (int s = 0; s < 512; s++)
        acc += beta[s] * Vp[(size_t)s * VLEN];
    g_part[((size_t)sc * B_ + b) * VLEN + v] = acc;
}

// ---------------- Kernel 6: reduce partials --------------------------------
__global__ void out_reduce_kernel(float* __restrict__ out) {
    int i = blockIdx.x * 256 + threadIdx.x;
    const int stride = B_ * VLEN;
    out[i] = g_part[i] + g_part[stride + i] + g_part[2 * stride + i] + g_part[3 * stride + i];
}

// ---------------- Launch ----------------
extern "C" void kernel_launch(void* const* d_in, const int* in_sizes, int n_in,
                              void* d_out, int out_size) {
    const float* h   = (const float*)d_in[0];   // [B, HLEN]
    const float* V   = (const float*)d_in[1];   // [B, S, VLEN]
    const float* W_w = (const float*)d_in[2];   // [HID, HLEN]
    const float* W_b = (const float*)d_in[3];   // [HID]
    const float* U_w = (const float*)d_in[4];   // [HID, VLEN]
    const float* w_w = (const float*)d_in[5];   // [HID]
    float* out = (float*)d_out;                 // [B, VLEN]

    __half* Vh; cudaGetSymbolAddress((void**)&Vh, g_Vh);
    __half* Uh; cudaGetSymbolAddress((void**)&Uh, g_Uh);

    cudaFuncSetAttribute(e_kernel, cudaFuncAttributeMaxDynamicSharedMemorySize, E_SMEM);

    // 1. fp32 -> fp16 conversions
    {
        size_t n4 = (size_t)B_ * S_ * VLEN / 4;
        cvt_kernel<<<(unsigned)((n4 + 255) / 256), 256>>>(V, Vh, n4);
        size_t u4 = (size_t)HID * VLEN / 4;
        cvt_kernel<<<(unsigned)((u4 + 255) / 256), 256>>>(U_w, Uh, u4);
    }
    // 2. h_proj
    hproj_kernel<<<(B_ * HID) / 8, 256>>>(h, W_w, W_b);
    // 3. fused e scores (pipelined HMMA)
    {
        dim3 grid(S_ / 128, B_);
        e_kernel<<<grid, 256, E_SMEM>>>(w_w);
    }
    // 4. softmax
    softmax_kernel<<<B_, 256>>>();
    // 5. weighted sum partials
    {
        dim3 grid(VLEN / 256, B_, 4);
        out_part_kernel<<<grid, 256>>>(V);
    }
    // 6. reduce
    out_reduce_kernel<<<(B_ * VLEN) / 256, 256>>>(out);
}

// round 9
// speedup vs baseline: 1.7109x; 1.1124x over previous
#include <cuda_runtime.h>
#include <cuda_fp16.h>
#include <cstdint>
#include <cstddef>

// ---------------- Problem constants ----------------
#define B_   32
#define S_   2048
#define HLEN 1024
#define VLEN 1024
#define HID  1024

// ---------------- Scratch (static device globals; no allocs allowed) ------
__device__ __align__(16) __half g_Vh[(size_t)B_ * S_ * VLEN];   // 128 MB
__device__ __align__(16) __half g_Uh[(size_t)HID * VLEN];       // 2 MB
__device__ __align__(16) float  g_hp[B_ * HID];                 // h_proj + bias
__device__ __align__(16) float  g_e[B_ * S_];                   // e scores -> beta
__device__ __align__(16) float  g_part[4 * B_ * VLEN];          // out partials

// ---------------- Helpers ----------------
__device__ __forceinline__ uint32_t smem_u32(const void* p) {
    return (uint32_t)__cvta_generic_to_shared(p);
}

__device__ __forceinline__ void ldsm_x4(uint32_t* r, uint32_t addr) {
    asm volatile("ldmatrix.sync.aligned.m8n8.x4.shared.b16 {%0,%1,%2,%3},[%4];"
                 : "=r"(r[0]), "=r"(r[1]), "=r"(r[2]), "=r"(r[3]) : "r"(addr));
}

__device__ __forceinline__ void mma16816(float* c, const uint32_t* a, const uint32_t* b) {
    asm volatile(
        "mma.sync.aligned.m16n8k16.row.col.f32.f16.f16.f32 "
        "{%0,%1,%2,%3},{%4,%5,%6,%7},{%8,%9},{%0,%1,%2,%3};"
        : "+f"(c[0]), "+f"(c[1]), "+f"(c[2]), "+f"(c[3])
        : "r"(a[0]), "r"(a[1]), "r"(a[2]), "r"(a[3]), "r"(b[0]), "r"(b[1]));
}

__device__ __forceinline__ void cp_async16(uint32_t dst, const void* src) {
    asm volatile("cp.async.cg.shared.global [%0], [%1], 16;" :: "r"(dst), "l"(src) : "memory");
}
#define CP_COMMIT() asm volatile("cp.async.commit_group;" ::: "memory")
#define CP_WAIT(n)  asm volatile("cp.async.wait_group %0;" :: "n"(n) : "memory")

__device__ __forceinline__ float tanh_fast(float x) {
    float y; asm("tanh.approx.f32 %0, %1;" : "=f"(y) : "f"(x)); return y;
}

// ---------------- Kernel 1: fp32 -> fp16 convert ----------------
__global__ void cvt_kernel(const float* __restrict__ src, __half* __restrict__ dst, size_t n4) {
    size_t i = (size_t)blockIdx.x * blockDim.x + threadIdx.x;
    if (i >= n4) return;
    float4 v = reinterpret_cast<const float4*>(src)[i];
    __half2* d2 = reinterpret_cast<__half2*>(dst) + i * 2;
    d2[0] = __floats2half2_rn(v.x, v.y);
    d2[1] = __floats2half2_rn(v.z, v.w);
}

// ---------------- Kernel 2: h_proj[b,d] = h[b]·W_w[d] + W_b[d] ------------
__global__ void hproj_kernel(const float* __restrict__ h,
                             const float* __restrict__ Ww,
                             const float* __restrict__ Wb) {
    int w = (blockIdx.x * blockDim.x + threadIdx.x) >> 5;
    int lane = threadIdx.x & 31;
    int b = w >> 10;
    int d = w & 1023;
    if (b >= B_) return;
    const float* hv = h + (size_t)b * HLEN;
    const float* wr = Ww + (size_t)d * HLEN;
    float acc = 0.f;
    #pragma unroll 8
    for (int v = lane; v < HLEN; v += 32) acc += hv[v] * wr[v];
    #pragma unroll
    for (int o = 16; o; o >>= 1) acc += __shfl_xor_sync(0xffffffffu, acc, o);
    if (lane == 0) g_hp[b * HID + d] = acc + Wb[d];
}

// ---------------- Kernel 3: fused e = w·tanh(hp + V U^T) ----------------
// 3-stage cp.async pipelined HMMA GEMM, all addressing hoisted.
// Block: 256 threads (8 warps: 4(M) x 2(N)). Tile M=128(s), N=128(d), K=64.
// grid = (S/128, B). 2 CTAs/SM.
#define BK 64
#define STAGES 3
#define STAGE_BYTES (2 * 128 * BK * 2)   // 32768 (A 16K + B 16K)
#define E_SMEM (STAGES * STAGE_BYTES + 512)

__global__ void __launch_bounds__(256, 2) e_kernel(const float* __restrict__ ww) {
    extern __shared__ char smem[];
    float* e_red = reinterpret_cast<float*>(smem + STAGES * STAGE_BYTES);

    const int tid  = threadIdx.x;
    const int lane = tid & 31;
    const int warp = tid >> 5;
    const int wm = warp & 3;     // 0..3 -> 32 rows each
    const int wn = warp >> 2;    // 0..1 -> 64 cols each
    const int b  = blockIdx.y;
    const int s0 = blockIdx.x * 128;

    const char* Abytes = reinterpret_cast<const char*>(g_Vh + ((size_t)b * S_ + s0) * VLEN);
    const char* Ubytes = reinterpret_cast<const char*>(g_Uh);
    const float* hpb   = g_hp + b * HID;

    if (tid < 128) e_red[tid] = 0.f;

    // ---- loader precompute: j in 0..3 => A chunks, j in 4..7 => B chunks ----
    // i = tid + j*256 ; row = (tid>>3) + (j&3)*32 ; c16 = tid&7 (row&7 invariant in j)
    const uint32_t row_lo = tid >> 3;          // 0..31
    const uint32_t c16    = tid & 7;
    const uint32_t scol   = ((c16 << 4) ^ ((row_lo & 7) << 4));
    uint32_t soff[4], goff[4];
    #pragma unroll
    for (int j = 0; j < 4; ++j) {
        soff[j] = (row_lo << 7) + (j << 12) + scol;       // swizzled smem offset
        goff[j] = row_lo * 2048 + (j << 16) + (c16 << 4); // gmem byte offset
    }

    auto issue = [&](int t) {
        const uint32_t sb = smem_u32(smem + (t % STAGES) * STAGE_BYTES);
        const uint32_t kb = (uint32_t)(t & 15) << 7;       // k advance (bytes)
        const uint32_t nb = (uint32_t)(t >> 4) << 18;      // n-block advance for B
        #pragma unroll
        for (int j = 0; j < 4; ++j)
            cp_async16(sb + soff[j], Abytes + goff[j] + kb);
        #pragma unroll
        for (int j = 0; j < 4; ++j)
            cp_async16(sb + 16384 + soff[j], Ubytes + goff[j] + kb + nb);
        CP_COMMIT();
    };

    // ---- ldmatrix address precompute ----
    // addr = stage + rowbase + (colbyte ^ xormask); colbyte = ks*32 + lane-part
    uint32_t abase[2], axor[2];
    #pragma unroll
    for (int mf = 0; mf < 2; ++mf) {
        const uint32_t row = wm * 32 + mf * 16 + (lane & 15);
        abase[mf] = row << 7;
        axor[mf]  = (row & 7) << 4;
    }
    const uint32_t acol0 = (lane >> 4) << 4;
    uint32_t bbase[4], bxor[4];
    #pragma unroll
    for (int nf2 = 0; nf2 < 4; ++nf2) {
        const uint32_t row = wn * 64 + nf2 * 16 + ((lane >> 4) << 3) + (lane & 7);
        bbase[nf2] = row << 7;
        bxor[nf2]  = (row & 7) << 4;
    }
    const uint32_t bcol0 = ((lane >> 3) & 1) << 4;

    issue(0);
    issue(1);

    float acc[2][8][4] = {};
    float e_part[4] = {0.f, 0.f, 0.f, 0.f};

    for (int t = 0; t < 128; ++t) {
        CP_WAIT(1);            // tile t resident (t+1 may still be in flight)
        __syncthreads();       // all warps done reading stage (t+2)%3
        if (t + 2 < 128) issue(t + 2);

        const uint32_t stg  = smem_u32(smem + (t % STAGES) * STAGE_BYTES);
        const uint32_t stgB = stg + 16384;

        #pragma unroll
        for (int ks = 0; ks < 4; ++ks) {
            const uint32_t kcol = (uint32_t)ks << 5;
            uint32_t a[2][4];
            #pragma unroll
            for (int mf = 0; mf < 2; ++mf)
                ldsm_x4(a[mf], stg + abase[mf] + ((kcol + acol0) ^ axor[mf]));
            uint32_t bb[4][4];
            #pragma unroll
            for (int nf2 = 0; nf2 < 4; ++nf2)
                ldsm_x4(bb[nf2], stgB + bbase[nf2] + ((kcol + bcol0) ^ bxor[nf2]));
            #pragma unroll
            for (int mf = 0; mf < 2; ++mf)
                #pragma unroll
                for (int nf = 0; nf < 8; ++nf)
                    mma16816(acc[mf][nf], a[mf], &bb[nf >> 1][(nf & 1) * 2]);
        }

        if ((t & 15) == 15) {
            // ---- fold tanh + w_w dot on this 128-col n-block, reset acc ----
            const int n0 = (t >> 4) << 7;
            const int cb = (n0 + wn * 64) >> 1;  // float2 index base
            const float2* hp2 = reinterpret_cast<const float2*>(hpb);
            const float2* ww2 = reinterpret_cast<const float2*>(ww);
            #pragma unroll
            for (int nf = 0; nf < 8; ++nf) {
                const int ci = cb + nf * 4 + (lane & 3);
                const float2 hh = hp2[ci];
                const float2 wv = ww2[ci];
                #pragma unroll
                for (int mf = 0; mf < 2; ++mf) {
                    e_part[mf * 2 + 0] += tanh_fast(acc[mf][nf][0] + hh.x) * wv.x
                                        + tanh_fast(acc[mf][nf][1] + hh.y) * wv.y;
                    e_part[mf * 2 + 1] += tanh_fast(acc[mf][nf][2] + hh.x) * wv.x
                                        + tanh_fast(acc[mf][nf][3] + hh.y) * wv.y;
                    acc[mf][nf][0] = 0.f; acc[mf][nf][1] = 0.f;
                    acc[mf][nf][2] = 0.f; acc[mf][nf][3] = 0.f;
                }
            }
        }
    }

    // reduce over the 4 lanes sharing each row
    #pragma unroll
    for (int i = 0; i < 4; i++) {
        e_part[i] += __shfl_xor_sync(0xffffffffu, e_part[i], 1);
        e_part[i] += __shfl_xor_sync(0xffffffffu, e_part[i], 2);
    }
    if ((lane & 3) == 0) {
        #pragma unroll
        for (int i = 0; i < 4; i++) {
            const int r = wm * 32 + (i >> 1) * 16 + (i & 1) * 8 + (lane >> 2);
            atomicAdd(&e_red[r], e_part[i]);
        }
    }
    __syncthreads();
    if (tid < 128)
        g_e[(size_t)b * S_ + s0 + tid] = e_red[tid];
}

// ---------------- Kernel 4: softmax over S (in-place on g_e) -------------
__global__ void softmax_kernel() {
    int b = blockIdx.x;
    float* row = g_e + (size_t)b * S_;
    __shared__ float red[256];
    float m = -1e30f;
    for (int s = threadIdx.x; s < S_; s += 256) m = fmaxf(m, row[s]);
    red[threadIdx.x] = m; __syncthreads();
    for (int o = 128; o > 0; o >>= 1) {
        if (threadIdx.x < o) red[threadIdx.x] = fmaxf(red[threadIdx.x], red[threadIdx.x + o]);
        __syncthreads();
    }
    m = red[0]; __syncthreads();
    float sum = 0.f;
    for (int s = threadIdx.x; s < S_; s += 256) {
        float v = __expf(row[s] - m);
        row[s] = v;
        sum += v;
    }
    red[threadIdx.x] = sum; __syncthreads();
    for (int o = 128; o > 0; o >>= 1) {
        if (threadIdx.x < o) red[threadIdx.x] += red[threadIdx.x + o];
        __syncthreads();
    }
    float inv = 1.f / red[0];
    for (int s = threadIdx.x; s < S_; s += 256) row[s] *= inv;
}

// ---------------- Kernel 5: out partials over s-splits (fp16 V) -----------
// grid (2 v2chunks, B, 4 schunks), 256 threads; each thread owns one half2 col.
__global__ void out_part_kernel() {
    int vc = blockIdx.x, b = blockIdx.y, sc = blockIdx.z;
    int v2 = vc * 256 + threadIdx.x;             // 0..511 half2 columns
    const float* beta = g_e + (size_t)b * S_ + sc * 512;
    const __half2* Vp = reinterpret_cast<const __half2*>(g_Vh)
                      + ((size_t)b * S_ + sc * 512) * (VLEN / 2) + v2;
    float ax = 0.f, ay = 0.f;
    #pragma unroll 8
    for (int s = 0; s < 512; s++) {
        const float bt = beta[s];
        const float2 vv = __half22float2(Vp[(size_t)s * (VLEN / 2)]);
        ax += bt * vv.x;
        ay += bt * vv.y;
    }
    float2* dst = reinterpret_cast<float2*>(g_part) + ((size_t)sc * B_ + b) * (VLEN / 2) + v2;
    *dst = make_float2(ax, ay);
}

// ---------------- Kernel 6: reduce partials --------------------------------
__global__ void out_reduce_kernel(float* __restrict__ out) {
    int i = blockIdx.x * 256 + threadIdx.x;
    const int stride = B_ * VLEN;
    out[i] = g_part[i] + g_part[stride + i] + g_part[2 * stride + i] + g_part[3 * stride + i];
}

// ---------------- Launch ----------------
extern "C" void kernel_launch(void* const* d_in, const int* in_sizes, int n_in,
                              void* d_out, int out_size) {
    const float* h   = (const float*)d_in[0];   // [B, HLEN]
    const float* V   = (const float*)d_in[1];   // [B, S, VLEN]
    const float* W_w = (const float*)d_in[2];   // [HID, HLEN]
    const float* W_b = (const float*)d_in[3];   // [HID]
    const float* U_w = (const float*)d_in[4];   // [HID, VLEN]
    const float* w_w = (const float*)d_in[5];   // [HID]
    float* out = (float*)d_out;                 // [B, VLEN]

    __half* Vh; cudaGetSymbolAddress((void**)&Vh, g_Vh);
    __half* Uh; cudaGetSymbolAddress((void**)&Uh, g_Uh);

    cudaFuncSetAttribute(e_kernel, cudaFuncAttributeMaxDynamicSharedMemorySize, E_SMEM);

    // 1. fp32 -> fp16 conversions
    {
        size_t n4 = (size_t)B_ * S_ * VLEN / 4;
        cvt_kernel<<<(unsigned)((n4 + 255) / 256), 256>>>(V, Vh, n4);
        size_t u4 = (size_t)HID * VLEN / 4;
        cvt_kernel<<<(unsigned)((u4 + 255) / 256), 256>>>(U_w, Uh, u4);
    }
    // 2. h_proj
    hproj_kernel<<<(B_ * HID) / 8, 256>>>(h, W_w, W_b);
    // 3. fused e scores (pipelined HMMA)
    {
        dim3 grid(S_ / 128, B_);
        e_kernel<<<grid, 256, E_SMEM>>>(w_w);
    }
    // 4. softmax
    softmax_kernel<<<B_, 256>>>();
    // 5. weighted sum partials (fp16 V)
    {
        dim3 grid(2, B_, 4);
        out_part_kernel<<<grid, 256>>>();
    }
    // 6. reduce
    out_reduce_kernel<<<(B_ * VLEN) / 256, 256>>>(out);
}

// round 10
// speedup vs baseline: 1.7765x; 1.0383x over previous
#include <cuda_runtime.h>
#include <cuda_fp16.h>
#include <cstdint>
#include <cstddef>

// ---------------- Problem constants ----------------
#define B_   32
#define S_   2048
#define HLEN 1024
#define VLEN 1024
#define HID  1024

// ---------------- Scratch (static device globals; no allocs allowed) ------
// g_Vh: tiled layout. Tile (b, sblk 0..7, kt 0..15) = 256 rows x 64 cols fp16,
//       stored as the exact swizzled 32KB smem image, contiguous.
// g_Uh: tiled layout. Tile (nb 0..7, kt 0..15) = 128 rows x 64 cols fp16, 16KB.
__device__ __align__(16) __half g_Vh[(size_t)B_ * S_ * VLEN];   // 128 MB
__device__ __align__(16) __half g_Uh[(size_t)HID * VLEN];       // 2 MB
__device__ __align__(16) float  g_hp[B_ * HID];                 // h_proj + bias
__device__ __align__(16) float  g_e[B_ * S_];                   // e scores -> beta
__device__ __align__(16) float  g_part[4 * B_ * VLEN];          // out partials

// ---------------- Helpers ----------------
__device__ __forceinline__ uint32_t smem_u32(const void* p) {
    return (uint32_t)__cvta_generic_to_shared(p);
}

__device__ __forceinline__ void ldsm_x4(uint32_t* r, uint32_t addr) {
    asm volatile("ldmatrix.sync.aligned.m8n8.x4.shared.b16 {%0,%1,%2,%3},[%4];"
                 : "=r"(r[0]), "=r"(r[1]), "=r"(r[2]), "=r"(r[3]) : "r"(addr));
}

__device__ __forceinline__ void mma16816(float* c, const uint32_t* a, const uint32_t* b) {
    asm volatile(
        "mma.sync.aligned.m16n8k16.row.col.f32.f16.f16.f32 "
        "{%0,%1,%2,%3},{%4,%5,%6,%7},{%8,%9},{%0,%1,%2,%3};"
        : "+f"(c[0]), "+f"(c[1]), "+f"(c[2]), "+f"(c[3])
        : "r"(a[0]), "r"(a[1]), "r"(a[2]), "r"(a[3]), "r"(b[0]), "r"(b[1]));
}

#define MBARRIER_INIT(addr, cnt) \
    asm volatile("mbarrier.init.shared.b64 [%0], %1;" :: "r"(addr), "r"(cnt) : "memory")
#define MBARRIER_ARRIVE(addr) \
    asm volatile("mbarrier.arrive.shared.b64 _, [%0];" :: "r"(addr) : "memory")

__device__ __forceinline__ void mbar_wait_parity(uint32_t mbar, uint32_t parity) {
    uint32_t done;
    asm volatile(
        "{\n\t.reg .pred p;\n\t"
        "mbarrier.try_wait.parity.acquire.cta.shared::cta.b64 p, [%1], %2;\n\t"
        "selp.b32 %0, 1, 0, p;\n\t}"
        : "=r"(done) : "r"(mbar), "r"(parity) : "memory");
    if (!done) {
        asm volatile(
            "{\n\t.reg .pred P1;\n\t"
            "WL_%=:\n\t"
            "mbarrier.try_wait.parity.acquire.cta.shared::cta.b64 P1, [%0], %1, 0x989680;\n\t"
            "@P1 bra.uni WD_%=;\n\t"
            "bra.uni WL_%=;\n\t"
            "WD_%=:\n\t}"
            :: "r"(mbar), "r"(parity) : "memory");
    }
}

__device__ __forceinline__ void bulk_ld(uint32_t dst, const void* src, uint32_t bytes, uint32_t mbar) {
    asm volatile(
        "cp.async.bulk.shared::cluster.global.mbarrier::complete_tx::bytes [%0], [%1], %2, [%3];"
        :: "r"(dst), "l"(src), "r"(bytes), "r"(mbar) : "memory");
}

__device__ __forceinline__ float tanh_fast(float x) {
    float y; asm("tanh.approx.f32 %0, %1;" : "=f"(y) : "f"(x)); return y;
}

__device__ __forceinline__ uint32_t pack_h2(float x, float y) {
    __half2 h = __floats2half2_rn(x, y);
    return *reinterpret_cast<uint32_t*>(&h);
}

// ---------------- Kernel 1a: V fp32 -> tiled/swizzled fp16 -------------
// grid 4096 blocks (b*128 + sblk*16 + kt), 256 threads. Tile 256x64.
__global__ void cvt_v_kernel(const float* __restrict__ V) {
    const int blk = blockIdx.x;
    const int b  = blk >> 7;
    const int sb = (blk >> 4) & 7;
    const int kt = blk & 15;
    const float* src = V + ((size_t)b * S_ + sb * 256) * VLEN + kt * 64;
    char* dst = reinterpret_cast<char*>(g_Vh) + (((size_t)(b * 8 + sb) * 16 + kt) << 15);

    const int t = threadIdx.x;
    const int rowq = t >> 2;       // 0..63
    const int cq   = t & 3;        // 16-float column group
    #pragma unroll
    for (int p = 0; p < 4; ++p) {
        const int row = rowq + p * 64;
        const float4* s4 = reinterpret_cast<const float4*>(src + (size_t)row * VLEN + cq * 16);
        #pragma unroll
        for (int j = 0; j < 2; ++j) {
            const float4 f0 = s4[j * 2], f1 = s4[j * 2 + 1];
            uint4 hv;
            hv.x = pack_h2(f0.x, f0.y); hv.y = pack_h2(f0.z, f0.w);
            hv.z = pack_h2(f1.x, f1.y); hv.w = pack_h2(f1.z, f1.w);
            uint32_t off = (row << 7) + cq * 32 + j * 16;
            off ^= (off >> 3) & 0x70;
            *reinterpret_cast<uint4*>(dst + off) = hv;
        }
    }
}

// ---------------- Kernel 1b: U fp32 -> tiled/swizzled fp16 -------------
// grid 128 blocks (nb*16 + kt), 256 threads. Tile 128x64.
__global__ void cvt_u_kernel(const float* __restrict__ U) {
    const int blk = blockIdx.x;
    const int nb = blk >> 4;
    const int kt = blk & 15;
    const float* src = U + (size_t)(nb * 128) * VLEN + kt * 64;
    char* dst = reinterpret_cast<char*>(g_Uh) + ((size_t)blk << 14);

    const int t = threadIdx.x;
    const int row = t >> 1;        // 0..127
    const int cq  = t & 1;         // 32-float column group
    const float4* s4 = reinterpret_cast<const float4*>(src + (size_t)row * VLEN + cq * 32);
    #pragma unroll
    for (int j = 0; j < 4; ++j) {
        const float4 f0 = s4[j * 2], f1 = s4[j * 2 + 1];
        uint4 hv;
        hv.x = pack_h2(f0.x, f0.y); hv.y = pack_h2(f0.z, f0.w);
        hv.z = pack_h2(f1.x, f1.y); hv.w = pack_h2(f1.z, f1.w);
        uint32_t off = (row << 7) + cq * 64 + j * 16;
        off ^= (off >> 3) & 0x70;
        *reinterpret_cast<uint4*>(dst + off) = hv;
    }
}

// ---------------- Kernel 2: h_proj[b,d] = h[b]·W_w[d] + W_b[d] ------------
__global__ void hproj_kernel(const float* __restrict__ h,
                             const float* __restrict__ Ww,
                             const float* __restrict__ Wb) {
    int w = (blockIdx.x * blockDim.x + threadIdx.x) >> 5;
    int lane = threadIdx.x & 31;
    int b = w >> 10;
    int d = w & 1023;
    if (b >= B_) return;
    const float* hv = h + (size_t)b * HLEN;
    const float* wr = Ww + (size_t)d * HLEN;
    float acc = 0.f;
    #pragma unroll 8
    for (int v = lane; v < HLEN; v += 32) acc += hv[v] * wr[v];
    #pragma unroll
    for (int o = 16; o; o >>= 1) acc += __shfl_xor_sync(0xffffffffu, acc, o);
    if (lane == 0) g_hp[b * HID + d] = acc + Wb[d];
}

// ---------------- Kernel 3: fused e = w·tanh(hp + V U^T) ----------------
// Bulk-DMA mbarrier pipeline. 512 threads (16 warps: 8(M) x 2(N)), 1 CTA/SM.
// Tile M=256(s), N=128(d), K=64. 3 stages x (A 32KB + B 16KB). grid=(8, 32).
#define NTILES 128
#define STAGE_SZ 49152
#define SMEM_STAGE0 2048
#define E_SMEM (SMEM_STAGE0 + 3 * STAGE_SZ)

__global__ void __launch_bounds__(512, 1) e_kernel(const float* __restrict__ ww) {
    extern __shared__ char smem[];
    const uint32_t sbase = smem_u32(smem);
    float* e_red = reinterpret_cast<float*>(smem + 64);   // 256 floats

    const int tid  = threadIdx.x;
    const int lane = tid & 31;
    const int warp = tid >> 5;
    const int wm = warp & 7;     // 0..7 -> 32 rows each (256 total)
    const int wn = warp >> 3;    // 0..1 -> 64 cols each
    const int b  = blockIdx.y;
    const int sb = blockIdx.x;   // s-block of 256

    const uint32_t full0  = sbase;        // 3 x 8B
    const uint32_t empty0 = sbase + 24;   // 3 x 8B

    if (tid == 0) {
        #pragma unroll
        for (int s = 0; s < 3; s++) {
            MBARRIER_INIT(full0 + s * 8, 1);
            MBARRIER_INIT(empty0 + s * 8, 16);
        }
    }
    if (tid < 256) e_red[tid] = 0.f;
    __syncthreads();

    const char* Ab = reinterpret_cast<const char*>(g_Vh) + (((size_t)(b * 8 + sb) * 16) << 15);
    const char* Bb = reinterpret_cast<const char*>(g_Uh);
    const float* hpb = g_hp + b * HID;

    // ---- producer: single thread, 2 bulk copies per tile ----
    auto produce = [&](int c) {
        const int s = c % 3, r = c / 3;
        if (r >= 1) mbar_wait_parity(empty0 + s * 8, (uint32_t)(r - 1) & 1);
        const uint32_t mb = full0 + s * 8;
        asm volatile("mbarrier.arrive.expect_tx.shared.b64 _, [%0], %1;"
                     :: "r"(mb), "r"(49152u) : "memory");
        const uint32_t dstA = sbase + SMEM_STAGE0 + s * STAGE_SZ;
        bulk_ld(dstA,         Ab + ((size_t)(c & 15) << 15), 32768u, mb);
        bulk_ld(dstA + 32768, Bb + ((size_t)((c >> 4) * 16 + (c & 15)) << 14), 16384u, mb);
    };

    if (tid == 0) { produce(0); produce(1); }

    // ---- ldmatrix address precompute ----
    uint32_t abase[2], axor[2];
    #pragma unroll
    for (int mf = 0; mf < 2; ++mf) {
        const uint32_t row = wm * 32 + mf * 16 + (lane & 15);
        abase[mf] = row << 7;
        axor[mf]  = (row & 7) << 4;
    }
    const uint32_t acol0 = (lane >> 4) << 4;
    uint32_t bbase[4], bxor[4];
    #pragma unroll
    for (int nf2 = 0; nf2 < 4; ++nf2) {
        const uint32_t row = wn * 64 + nf2 * 16 + ((lane >> 4) << 3) + (lane & 7);
        bbase[nf2] = row << 7;
        bxor[nf2]  = (row & 7) << 4;
    }
    const uint32_t bcol0 = ((lane >> 3) & 1) << 4;

    float acc[2][8][4] = {};
    float e_part[4] = {0.f, 0.f, 0.f, 0.f};

    for (int t = 0; t < NTILES; ++t) {
        if (tid == 0 && t + 2 < NTILES) produce(t + 2);

        mbar_wait_parity(full0 + (t % 3) * 8, (uint32_t)(t / 3) & 1);

        const uint32_t stg  = sbase + SMEM_STAGE0 + (t % 3) * STAGE_SZ;
        const uint32_t stgB = stg + 32768;

        #pragma unroll
        for (int ks = 0; ks < 4; ++ks) {
            const uint32_t kcol = (uint32_t)ks << 5;
            uint32_t a[2][4];
            #pragma unroll
            for (int mf = 0; mf < 2; ++mf)
                ldsm_x4(a[mf], stg + abase[mf] + ((kcol + acol0) ^ axor[mf]));
            uint32_t bb[4][4];
            #pragma unroll
            for (int nf2 = 0; nf2 < 4; ++nf2)
                ldsm_x4(bb[nf2], stgB + bbase[nf2] + ((kcol + bcol0) ^ bxor[nf2]));
            #pragma unroll
            for (int mf = 0; mf < 2; ++mf)
                #pragma unroll
                for (int nf = 0; nf < 8; ++nf)
                    mma16816(acc[mf][nf], a[mf], &bb[nf >> 1][(nf & 1) * 2]);
        }

        if (lane == 0) MBARRIER_ARRIVE(empty0 + (t % 3) * 8);

        if ((t & 15) == 15) {
            // ---- fold tanh + w_w dot on this 128-col n-block, reset acc ----
            const int n0 = (t >> 4) << 7;
            const int cb = (n0 + wn * 64) >> 1;  // float2 index base
            const float2* hp2 = reinterpret_cast<const float2*>(hpb);
            const float2* ww2 = reinterpret_cast<const float2*>(ww);
            #pragma unroll
            for (int nf = 0; nf < 8; ++nf) {
                const int ci = cb + nf * 4 + (lane & 3);
                const float2 hh = hp2[ci];
                const float2 wv = ww2[ci];
                #pragma unroll
                for (int mf = 0; mf < 2; ++mf) {
                    e_part[mf * 2 + 0] += tanh_fast(acc[mf][nf][0] + hh.x) * wv.x
                                        + tanh_fast(acc[mf][nf][1] + hh.y) * wv.y;
                    e_part[mf * 2 + 1] += tanh_fast(acc[mf][nf][2] + hh.x) * wv.x
                                        + tanh_fast(acc[mf][nf][3] + hh.y) * wv.y;
                    acc[mf][nf][0] = 0.f; acc[mf][nf][1] = 0.f;
                    acc[mf][nf][2] = 0.f; acc[mf][nf][3] = 0.f;
                }
            }
        }
    }

    // reduce over the 4 lanes sharing each row
    #pragma unroll
    for (int i = 0; i < 4; i++) {
        e_part[i] += __shfl_xor_sync(0xffffffffu, e_part[i], 1);
        e_part[i] += __shfl_xor_sync(0xffffffffu, e_part[i], 2);
    }
    if ((lane & 3) == 0) {
        #pragma unroll
        for (int i = 0; i < 4; i++) {
            const int r = wm * 32 + (i >> 1) * 16 + (i & 1) * 8 + (lane >> 2);
            atomicAdd(&e_red[r], e_part[i]);
        }
    }
    __syncthreads();
    if (tid < 256)
        g_e[(size_t)b * S_ + sb * 256 + tid] = e_red[tid];
}

// ---------------- Kernel 4: softmax over S (in-place on g_e) -------------
__global__ void softmax_kernel() {
    int b = blockIdx.x;
    float* row = g_e + (size_t)b * S_;
    __shared__ float red[256];
    float m = -1e30f;
    for (int s = threadIdx.x; s < S_; s += 256) m = fmaxf(m, row[s]);
    red[threadIdx.x] = m; __syncthreads();
    for (int o = 128; o > 0; o >>= 1) {
        if (threadIdx.x < o) red[threadIdx.x] = fmaxf(red[threadIdx.x], red[threadIdx.x + o]);
        __syncthreads();
    }
    m = red[0]; __syncthreads();
    float sum = 0.f;
    for (int s = threadIdx.x; s < S_; s += 256) {
        float v = __expf(row[s] - m);
        row[s] = v;
        sum += v;
    }
    red[threadIdx.x] = sum; __syncthreads();
    for (int o = 128; o > 0; o >>= 1) {
        if (threadIdx.x < o) red[threadIdx.x] += red[threadIdx.x + o];
        __syncthreads();
    }
    float inv = 1.f / red[0];
    for (int s = threadIdx.x; s < S_; s += 256) row[s] *= inv;
}

// ---------------- Kernel 5: out partials over s-splits (tiled fp16 V) ----
// grid (2, B, 4), 256 threads; each thread owns one half2 column.
__global__ void out_part_kernel() {
    const int vc = blockIdx.x, b = blockIdx.y, sc = blockIdx.z;
    const int v2 = vc * 256 + threadIdx.x;     // half2 col 0..511
    const int kt = v2 >> 5;                    // 64-col tile index
    const uint32_t coff = (v2 & 31) << 2;
    const float* beta = g_e + (size_t)b * S_ + sc * 512;
    const char* base = reinterpret_cast<const char*>(g_Vh);

    float ax = 0.f, ay = 0.f;
    #pragma unroll 2
    for (int half = 0; half < 2; ++half) {
        const int sblk = sc * 2 + half;        // s-block of 256
        const char* tile = base + (((size_t)(b * 8 + sblk) * 16 + kt) << 15);
        #pragma unroll 8
        for (int r = 0; r < 256; ++r) {
            uint32_t off = (r << 7) + coff;
            off ^= (off >> 3) & 0x70;
            const float2 vv = __half22float2(*reinterpret_cast<const __half2*>(tile + off));
            const float bt = beta[half * 256 + r];
            ax += bt * vv.x;
            ay += bt * vv.y;
        }
    }
    float2* dst = reinterpret_cast<float2*>(g_part) + ((size_t)sc * B_ + b) * (VLEN / 2) + v2;
    *dst = make_float2(ax, ay);
}

// ---------------- Kernel 6: reduce partials --------------------------------
__global__ void out_reduce_kernel(float* __restrict__ out) {
    int i = blockIdx.x * 256 + threadIdx.x;
    const int stride = B_ * VLEN;
    out[i] = g_part[i] + g_part[stride + i] + g_part[2 * stride + i] + g_part[3 * stride + i];
}

// ---------------- Launch ----------------
extern "C" void kernel_launch(void* const* d_in, const int* in_sizes, int n_in,
                              void* d_out, int out_size) {
    const float* h   = (const float*)d_in[0];   // [B, HLEN]
    const float* V   = (const float*)d_in[1];   // [B, S, VLEN]
    const float* W_w = (const float*)d_in[2];   // [HID, HLEN]
    const float* W_b = (const float*)d_in[3];   // [HID]
    const float* U_w = (const float*)d_in[4];   // [HID, VLEN]
    const float* w_w = (const float*)d_in[5];   // [HID]
    float* out = (float*)d_out;                 // [B, VLEN]

    cudaFuncSetAttribute(e_kernel, cudaFuncAttributeMaxDynamicSharedMemorySize, E_SMEM);

    // 1. fp32 -> tiled/swizzled fp16
    cvt_v_kernel<<<4096, 256>>>(V);
    cvt_u_kernel<<<128, 256>>>(U_w);
    // 2. h_proj
    hproj_kernel<<<(B_ * HID) / 8, 256>>>(h, W_w, W_b);
    // 3. fused e scores (bulk-DMA mbarrier pipelined HMMA)
    {
        dim3 grid(8, B_);
        e_kernel<<<grid, 512, E_SMEM>>>(w_w);
    }
    // 4. softmax
    softmax_kernel<<<B_, 256>>>();
    // 5. weighted sum partials (tiled fp16 V)
    {
        dim3 grid(2, B_, 4);
        out_part_kernel<<<grid, 256>>>();
    }
    // 6. reduce
    out_reduce_kernel<<<(B_ * VLEN) / 256, 256>>>(out);
}